// round 17
// baseline (speedup 1.0000x reference)
#include <cuda_runtime.h>
#include <cuda_bf16.h>
#include <cuda_fp16.h>
#include <cstdint>

#define Bb   256
#define Tt   64
#define OBSn 4096
#define Dd   1024
#define Aa   8
#define Hh   2048
#define ZLn  4
#define ZDn  256
#define BT   (Bb*Tt)          // 16384
#define EPSf 1e-5f
#define JEW_LD (Dd + Aa)      // 1032

typedef __half f16;

// ---------------- scratch (static device globals; no allocation) -------------
__device__ float g_h1[BT * Hh];
__device__ float g_h [Bb * Dd];
__device__ float g_xbn[BT * Dd];      // enc2 raw (pre-BN) reuse buffer
__device__ float g_d1[Bb * Hh];
__device__ float g_d2[Bb * OBSn];
__device__ float g_mean[4096];
__device__ float g_var [4096];
__device__ float g_wscan[4 * Dd * Dd];
__device__ float g_M2[3 * Dd * Aa];
__device__ float g_c [3 * Dd];
__device__ unsigned g_bar_cnt;

// fp16 buffers (single-digit throughout)
__device__ f16 g_obsH[BT * OBSn];
__device__ f16 g_w1  [Hh * OBSn];
__device__ f16 g_h1H [BT * Hh];
__device__ f16 g_w2  [Dd * Hh];
__device__ f16 g_xH  [BT * Dd];
__device__ f16 g_wih [3 * Dd * Dd];
__device__ f16 g_gi16[BT * 3 * Dd];
__device__ f16 g_zH  [Bb * Dd];
__device__ f16 g_d1H [Bb * Hh];
__device__ f16 g_dw1 [Hh * Dd];
__device__ f16 g_dw2 [OBSn * Hh];
__device__ f16 g_wsf [4 * Dd * Dd];               // PERMUTED rows 4d+comp
__device__ f16 g_hH  [Bb * Dd];

// ======================= PTX helpers =========================================
__device__ __forceinline__ uint32_t smem_u32(const void* p) {
    uint32_t a;
    asm("{ .reg .u64 t; cvta.to.shared.u64 t, %1; cvt.u32.u64 %0, t; }"
        : "=r"(a) : "l"(p));
    return a;
}
__device__ __forceinline__ void cp16(uint32_t s, const void* g) {
    asm volatile("cp.async.cg.shared.global [%0], [%1], 16;" :: "r"(s), "l"(g));
}
__device__ __forceinline__ void cp_commit() {
    asm volatile("cp.async.commit_group;" ::: "memory");
}
__device__ __forceinline__ void cp_wait0() {
    asm volatile("cp.async.wait_group 0;" ::: "memory");
}
__device__ __forceinline__ void cp_wait1() {
    asm volatile("cp.async.wait_group 1;" ::: "memory");
}
__device__ __forceinline__ void cp_wait2() {
    asm volatile("cp.async.wait_group 2;" ::: "memory");
}
__device__ __forceinline__ void ldm_x4(uint32_t* r, uint32_t a) {
    asm volatile("ldmatrix.sync.aligned.m8n8.x4.shared.b16 {%0,%1,%2,%3}, [%4];"
                 : "=r"(r[0]), "=r"(r[1]), "=r"(r[2]), "=r"(r[3]) : "r"(a));
}
__device__ __forceinline__ void mma_f16(float* c, const uint32_t* a, const uint32_t* b) {
    asm volatile("mma.sync.aligned.m16n8k16.row.col.f32.f16.f16.f32 "
                 "{%0,%1,%2,%3}, {%4,%5,%6,%7}, {%8,%9}, {%0,%1,%2,%3};"
                 : "+f"(c[0]), "+f"(c[1]), "+f"(c[2]), "+f"(c[3])
                 : "r"(a[0]), "r"(a[1]), "r"(a[2]), "r"(a[3]),
                   "r"(b[0]), "r"(b[1]));
}

// ====== WIDE fp16 GEMM: C = A @ B^T (+bias). CTA tile 128x256, 3-stage. ======
// Warp grid 2x4, warp tile 64x64: 32 MMAs per 8 ldmatrix per kh-half.
// A: MxK fp16; B: NxK fp16; C fp32 and/or C16 fp16. M%128==0, N%256==0, K%32==0.
#define LDW   40
#define WATILE (128 * LDW)
#define WBTILE (256 * LDW)
#define WSTG  (WATILE + WBTILE)
#define SMW_BYTES (3 * WSTG * 2)       // 92160

__global__ void __launch_bounds__(256)
mma_gemm16w(const f16* __restrict__ A, const f16* __restrict__ B,
            const float* __restrict__ bias, float* __restrict__ C,
            f16* __restrict__ C16, int M, int N, int K)
{
    extern __shared__ f16 smh[];

    const int tid = threadIdx.x;
    const int wid = tid >> 5, lane = tid & 31;
    const int wm = wid >> 2, wn = wid & 3;          // 2 x 4 warps, 64x64 tiles
    const int rowBase = blockIdx.y * 128, colBase = blockIdx.x * 256;
    const int NC = K >> 5;

    float acc[4][8][4];
#pragma unroll
    for (int i = 0; i < 4; i++)
#pragma unroll
        for (int j = 0; j < 8; j++)
#pragma unroll
            for (int k = 0; k < 4; k++) acc[i][j][k] = 0.f;

    auto load = [&](int c, int st) {
        const int koff = c << 5;
        f16* stp = smh + st * WSTG;
        {   // A: 128 rows x 32 cols -> 512 cp16
#pragma unroll
            for (int i = 0; i < 2; i++) {
                int u = tid * 2 + i;
                int row = u >> 2;
                int seg = (u & 3) << 3;
                cp16(smem_u32(stp + row * LDW + seg),
                     A + (size_t)(rowBase + row) * K + koff + seg);
            }
        }
        {   // B: 256 rows x 32 cols -> 1024 cp16
#pragma unroll
            for (int i = 0; i < 4; i++) {
                int u = tid * 4 + i;
                int row = u >> 2;
                int seg = (u & 3) << 3;
                cp16(smem_u32(stp + WATILE + row * LDW + seg),
                     B + (size_t)(colBase + row) * K + koff + seg);
            }
        }
        cp_commit();
    };

    load(0, 0);
    load(1, 1);
    for (int c = 0; c < NC; c++) {
        const int st = c % 3;
        if (c + 2 < NC) { load(c + 2, (c + 2) % 3); cp_wait2(); }
        else if (c + 1 < NC) cp_wait1();
        else cp_wait0();
        __syncthreads();

        const f16* stp = smh + st * WSTG;
#pragma unroll
        for (int kh = 0; kh < 2; kh++) {
            const int kcol = kh << 4;
            uint32_t a[4][4];
            uint32_t b[8][2];
            {
#pragma unroll
                for (int mt = 0; mt < 4; mt++) {
                    int r = wm * 64 + mt * 16 + (lane & 15);
                    int cc = kcol + ((lane >> 4) << 3);
                    ldm_x4(a[mt], smem_u32(stp + r * LDW + cc));
                }
            }
            {
                const f16* base = stp + WATILE;
#pragma unroll
                for (int np = 0; np < 4; np++) {
                    int r = wn * 64 + (np * 2 + (lane >> 4)) * 8 + (lane & 7);
                    int cc = kcol + (((lane >> 3) & 1) << 3);
                    uint32_t rr[4];
                    ldm_x4(rr, smem_u32(base + r * LDW + cc));
                    b[np * 2][0] = rr[0];     b[np * 2][1] = rr[1];
                    b[np * 2 + 1][0] = rr[2]; b[np * 2 + 1][1] = rr[3];
                }
            }
#pragma unroll
            for (int mt = 0; mt < 4; mt++)
#pragma unroll
                for (int nt = 0; nt < 8; nt++)
                    mma_f16(acc[mt][nt], a[mt], b[nt]);
        }
        __syncthreads();
    }

#pragma unroll
    for (int mt = 0; mt < 4; mt++) {
        const int row = rowBase + wm * 64 + mt * 16 + (lane >> 2);
#pragma unroll
        for (int nt = 0; nt < 8; nt++) {
            const int col = colBase + wn * 64 + nt * 8 + (lane & 3) * 2;
            float b0 = bias ? bias[col] : 0.f;
            float b1 = bias ? bias[col + 1] : 0.f;
            float v00 = acc[mt][nt][0] + b0, v01 = acc[mt][nt][1] + b1;
            float v10 = acc[mt][nt][2] + b0, v11 = acc[mt][nt][3] + b1;
            if (C) {
                *(float2*)(C + (size_t)row * N + col) = make_float2(v00, v01);
                *(float2*)(C + (size_t)(row + 8) * N + col) = make_float2(v10, v11);
            }
            if (C16) {
                *(__half2*)(C16 + (size_t)row * N + col) =
                    __halves2half2(__float2half_rn(v00), __float2half_rn(v01));
                *(__half2*)(C16 + (size_t)(row + 8) * N + col) =
                    __halves2half2(__float2half_rn(v10), __float2half_rn(v11));
            }
        }
    }
}

// ============ fp16 GEMM 128x128 (decoder): C = A @ B^T (+bias), 3-stage ======
#define LD2   40
#define TILE2 (128 * LD2)
#define STG16 (2 * TILE2)
#define SM16_BYTES (3 * STG16 * 2)     // 61440

__global__ void __launch_bounds__(256)
mma_gemm16(const f16* __restrict__ A, const f16* __restrict__ B,
           const float* __restrict__ bias, float* __restrict__ C,
           int M, int N, int K)
{
    extern __shared__ f16 smh[];

    const int tid = threadIdx.x;
    const int wid = tid >> 5, lane = tid & 31;
    const int wm = wid >> 2, wn = wid & 3;
    const int rowBase = blockIdx.y * 128, colBase = blockIdx.x * 128;
    const int NC = K >> 5;

    float acc[4][4][4];
#pragma unroll
    for (int i = 0; i < 4; i++)
#pragma unroll
        for (int j = 0; j < 4; j++)
#pragma unroll
            for (int k = 0; k < 4; k++) acc[i][j][k] = 0.f;

    const f16* srcs[2] = { A, B };
    const int  rbs [2] = { rowBase, colBase };

    auto load = [&](int c, int st) {
        const int koff = c << 5;
        f16* stp = smh + st * STG16;
#pragma unroll
        for (int tI = 0; tI < 2; tI++) {
#pragma unroll
            for (int i = 0; i < 2; i++) {
                int u = tid * 2 + i;
                int row = u >> 2;
                int seg = (u & 3) << 3;
                cp16(smem_u32(stp + tI * TILE2 + row * LD2 + seg),
                     srcs[tI] + (size_t)(rbs[tI] + row) * K + koff + seg);
            }
        }
        cp_commit();
    };

    load(0, 0);
    load(1, 1);
    for (int c = 0; c < NC; c++) {
        const int st = c % 3;
        if (c + 2 < NC) { load(c + 2, (c + 2) % 3); cp_wait2(); }
        else if (c + 1 < NC) cp_wait1();
        else cp_wait0();
        __syncthreads();

        const f16* stp = smh + st * STG16;
#pragma unroll
        for (int kh = 0; kh < 2; kh++) {
            const int kcol = kh << 4;
            uint32_t a[4][4];
            uint32_t b[4][2];
            {
#pragma unroll
                for (int mt = 0; mt < 4; mt++) {
                    int r = wm * 64 + mt * 16 + (lane & 15);
                    int cc = kcol + ((lane >> 4) << 3);
                    ldm_x4(a[mt], smem_u32(stp + r * LD2 + cc));
                }
            }
            {
                const f16* base = stp + TILE2;
#pragma unroll
                for (int np = 0; np < 2; np++) {
                    int r = wn * 32 + (np * 2 + (lane >> 4)) * 8 + (lane & 7);
                    int cc = kcol + (((lane >> 3) & 1) << 3);
                    uint32_t rr[4];
                    ldm_x4(rr, smem_u32(base + r * LD2 + cc));
                    b[np * 2][0] = rr[0];     b[np * 2][1] = rr[1];
                    b[np * 2 + 1][0] = rr[2]; b[np * 2 + 1][1] = rr[3];
                }
            }
#pragma unroll
            for (int mt = 0; mt < 4; mt++)
#pragma unroll
                for (int nt = 0; nt < 4; nt++)
                    mma_f16(acc[mt][nt], a[mt], b[nt]);
        }
        __syncthreads();
    }

#pragma unroll
    for (int mt = 0; mt < 4; mt++) {
        const int row = rowBase + wm * 64 + mt * 16 + (lane >> 2);
#pragma unroll
        for (int nt = 0; nt < 4; nt++) {
            const int col = colBase + wn * 32 + nt * 8 + (lane & 3) * 2;
            float b0 = bias ? bias[col] : 0.f;
            float b1 = bias ? bias[col + 1] : 0.f;
            *(float2*)(C + (size_t)row * N + col) =
                make_float2(acc[mt][nt][0] + b0, acc[mt][nt][1] + b1);
            *(float2*)(C + (size_t)(row + 8) * N + col) =
                make_float2(acc[mt][nt][2] + b0, acc[mt][nt][3] + b1);
        }
    }
}

// =================== persistent fused scan (fp16 single-digit h) =============
#define SLD    40
#define SATILE (128 * SLD)
#define SBTILE (64 * SLD)
#define SSTAGE (SATILE + SBTILE)
#define SLDF   68
#define SSM_BYTES 35840     // max(pipeline 30720, fp32 epi tile 128*68*4=34816)
#define NCTA_SCAN 128

__device__ __forceinline__ float sigmoidf_(float x) { return 1.f / (1.f + expf(-x)); }

__global__ void __launch_bounds__(256)
mma_scan_persist(const float* __restrict__ actions,
                 const float* __restrict__ je_w,
                 const float* __restrict__ je_b)
{
    extern __shared__ f16 ssm[];

    const int tid = threadIdx.x;
    const int wid = tid >> 5, lane = tid & 31;
    const int wm = wid & 3;
    const int wn = wid >> 2;
    const int rowBase = blockIdx.y * 128;
    const int colBase = blockIdx.x * 64;
    const int NC = Dd >> 5;   // 32

    const int dl = tid & 15;
    const int rg = tid >> 4;
    const int dg = (colBase >> 2) + dl;
    const float c0 = g_c[dg], c1 = g_c[Dd + dg], c2 = g_c[2 * Dd + dg];
    const float jb = je_b[dg];
    float m2r[8], m2z[8], m2n[8], jea[8];
#pragma unroll
    for (int j = 0; j < 8; j++) {
        m2r[j] = g_M2[(size_t)dg * 8 + j];
        m2z[j] = g_M2[(size_t)(Dd + dg) * 8 + j];
        m2n[j] = g_M2[(size_t)(2 * Dd + dg) * 8 + j];
        jea[j] = je_w[(size_t)dg * JEW_LD + Dd + j];
    }

    auto load = [&](int c, int st) {
        const int koff = c << 5;
        f16* stp = ssm + st * SSTAGE;
        {
#pragma unroll
            for (int i = 0; i < 2; i++) {
                int u = tid * 2 + i;
                int row = u >> 2;
                int seg = (u & 3) << 3;
                cp16(smem_u32(stp + row * SLD + seg),
                     g_hH + (size_t)(rowBase + row) * Dd + koff + seg);
            }
        }
        {
            int row = tid >> 2;
            int seg = (tid & 3) << 3;
            cp16(smem_u32(stp + SATILE + row * SLD + seg),
                 g_wsf + (size_t)(colBase + row) * Dd + koff + seg);
        }
        cp_commit();
    };

    for (int t = 0; t < Tt; t++) {
        float acc[2][4][4];
#pragma unroll
        for (int i = 0; i < 2; i++)
#pragma unroll
            for (int j = 0; j < 4; j++)
#pragma unroll
                for (int k = 0; k < 4; k++) acc[i][j][k] = 0.f;

        load(0, 0);
        int st = 0;
        for (int c = 0; c < NC; c++) {
            const bool more = (c + 1) < NC;
            if (more) { load(c + 1, st ^ 1); cp_wait1(); }
            else      { cp_wait0(); }
            __syncthreads();

            const f16* stp = ssm + st * SSTAGE;
#pragma unroll
            for (int kh = 0; kh < 2; kh++) {
                const int kcol = kh << 4;
                uint32_t a[2][4];
                uint32_t b[4][2];
                {
#pragma unroll
                    for (int mt = 0; mt < 2; mt++) {
                        int r = wm * 32 + mt * 16 + (lane & 15);
                        int cc = kcol + ((lane >> 4) << 3);
                        ldm_x4(a[mt], smem_u32(stp + r * SLD + cc));
                    }
                }
                {
                    const f16* base = stp + SATILE;
#pragma unroll
                    for (int np = 0; np < 2; np++) {
                        int r = wn * 32 + (np * 2 + (lane >> 4)) * 8 + (lane & 7);
                        int cc = kcol + (((lane >> 3) & 1) << 3);
                        uint32_t rr[4];
                        ldm_x4(rr, smem_u32(base + r * SLD + cc));
                        b[np * 2][0] = rr[0];     b[np * 2][1] = rr[1];
                        b[np * 2 + 1][0] = rr[2]; b[np * 2 + 1][1] = rr[3];
                    }
                }
#pragma unroll
                for (int mt = 0; mt < 2; mt++)
#pragma unroll
                    for (int nt = 0; nt < 4; nt++)
                        mma_f16(acc[mt][nt], a[mt], b[nt]);
            }
            __syncthreads();
            st ^= 1;
        }

        float* smf = (float*)ssm;
#pragma unroll
        for (int mt = 0; mt < 2; mt++) {
            const int row = wm * 32 + mt * 16 + (lane >> 2);
#pragma unroll
            for (int nt = 0; nt < 4; nt++) {
                const int col = wn * 32 + nt * 8 + (lane & 3) * 2;
                smf[row * SLDF + col]     = acc[mt][nt][0];
                smf[row * SLDF + col + 1] = acc[mt][nt][1];
                smf[(row + 8) * SLDF + col]     = acc[mt][nt][2];
                smf[(row + 8) * SLDF + col + 1] = acc[mt][nt][3];
            }
        }
        __syncthreads();

        const bool lastStep = (t == Tt - 1);
#pragma unroll
        for (int r8 = 0; r8 < 8; r8++) {
            const int row = rg * 8 + r8;
            const int b = rowBase + row;
            const int trow = b * Tt + t;

            float4 G4 = *(float4*)&smf[row * SLDF + 4 * dl];
            float hr = G4.x + c0;
            float hz = G4.y + c1;
            float hn = G4.z + c2;
            float hj = G4.w + jb;

            const float* a = actions + (size_t)trow * Aa;
#pragma unroll
            for (int j = 0; j < 8; j++) {
                float av = a[j];
                hr = fmaf(av, m2r[j], hr);
                hz = fmaf(av, m2z[j], hz);
                hn = fmaf(av, m2n[j], hn);
                hj = fmaf(av, jea[j], hj);
            }

            const f16* gi = g_gi16 + (size_t)trow * (3 * Dd);
            float r = sigmoidf_(__half2float(gi[dg]) + hr);
            float z = sigmoidf_(__half2float(gi[Dd + dg]) + hz);
            float n = tanhf(__half2float(gi[2 * Dd + dg]) + r * hn);
            float xv = __half2float(g_xH[(size_t)trow * Dd + dg]);
            float hnew = (1.f - z) * n + z * hj + xv;

            const int oi = b * Dd + dg;
            if (lastStep) g_h[oi] = hnew;
            g_hH[oi] = __float2half_rn(hnew);
        }

        __syncthreads();
        if (tid == 0) {
            __threadfence();
            atomicAdd(&g_bar_cnt, 1u);
            const unsigned target = (unsigned)(t + 1) * NCTA_SCAN;
            while (atomicAdd(&g_bar_cnt, 0u) < target) {}
            __threadfence();
        }
        __syncthreads();
    }
}

// =============== conversions =================================================
__global__ void cvt16_w(const float* __restrict__ X, f16* __restrict__ Xh, int n4)
{
    int i = blockIdx.x * blockDim.x + threadIdx.x;
    if (i >= n4) return;
    float4 v = ((const float4*)X)[i];
    __half2* H = (__half2*)Xh;
    H[2 * i]     = __halves2half2(__float2half_rn(v.x), __float2half_rn(v.y));
    H[2 * i + 1] = __halves2half2(__float2half_rn(v.z), __float2half_rn(v.w));
}
__global__ void cvt16_perm_ws()
{
    int i = blockIdx.x * blockDim.x + threadIdx.x;
    if (i >= 4 * Dd * Dd / 4) return;
    int flat = i * 4;
    int nrow = flat >> 10;
    int k = flat & 1023;
    int d = nrow >> 2, comp = nrow & 3;
    int orow = (comp < 3) ? comp * Dd + d : 3 * Dd + d;
    float4 v = *(const float4*)&g_wscan[(size_t)orow * Dd + k];
    __half2* H = (__half2*)g_wsf;
    H[2*i]   = __halves2half2(__float2half_rn(v.x), __float2half_rn(v.y));
    H[2*i+1] = __halves2half2(__float2half_rn(v.z), __float2half_rn(v.w));
}

// =============== SIMT GEMM (precompute only) ==================================
#define BKd 8
__global__ void __launch_bounds__(256)
sgemm_ab(const float* __restrict__ A, const float* __restrict__ Bm,
         float* __restrict__ C, int M, int N, int K, int lda, int ldb, int ldc)
{
    __shared__ float As[BKd][128];
    __shared__ float Bs[BKd][128];
    const int tid = threadIdx.x;
    const int tx = tid & 15, ty = tid >> 4;
    const int rowBase = blockIdx.y * 128, colBase = blockIdx.x * 128;
    const int lrA = tid >> 1, lcA = (tid & 1) * 4;
    const int kkB = tid >> 5, c4B = (tid & 31) * 4;
    const float* Aptr = A + (size_t)(rowBase + lrA) * lda + lcA;
    const float* Bptr = Bm + (size_t)kkB * ldb + colBase + c4B;
    float acc[8][8];
#pragma unroll
    for (int i = 0; i < 8; i++)
#pragma unroll
        for (int j = 0; j < 8; j++) acc[i][j] = 0.f;
    for (int k0 = 0; k0 < K; k0 += BKd) {
        float4 av = *(const float4*)(Aptr + k0);
        float4 bv = *(const float4*)(Bptr + (size_t)k0 * ldb);
        As[lcA+0][lrA]=av.x; As[lcA+1][lrA]=av.y;
        As[lcA+2][lrA]=av.z; As[lcA+3][lrA]=av.w;
        *(float4*)&Bs[kkB][c4B] = bv;
        __syncthreads();
#pragma unroll
        for (int kk = 0; kk < BKd; kk++) {
            float a[8], b[8];
#pragma unroll
            for (int i = 0; i < 8; i++) a[i] = As[kk][ty*8+i];
#pragma unroll
            for (int j = 0; j < 8; j++) b[j] = Bs[kk][tx*8+j];
#pragma unroll
            for (int i = 0; i < 8; i++)
#pragma unroll
                for (int j = 0; j < 8; j++)
                    acc[i][j] = fmaf(a[i], b[j], acc[i][j]);
        }
        __syncthreads();
    }
#pragma unroll
    for (int i = 0; i < 8; i++) {
        const int r = rowBase + ty * 8 + i;
#pragma unroll
        for (int j = 0; j < 8; j++)
            C[(size_t)r * ldc + colBase + tx * 8 + j] = acc[i][j];
    }
}

__global__ void copy_jew(const float* __restrict__ je_w)
{
    int idx = blockIdx.x * blockDim.x + threadIdx.x;
    if (idx >= Dd * Dd) return;
    int j = idx >> 10, k = idx & 1023;
    g_wscan[(size_t)(3 * Dd + j) * Dd + k] = je_w[(size_t)j * JEW_LD + k];
}

__global__ void __launch_bounds__(128)
m2c_k(const float* __restrict__ whh, const float* __restrict__ je_w,
      const float* __restrict__ je_b, const float* __restrict__ bhh)
{
    const int i = blockIdx.x;
    const int t = threadIdx.x;
    float acc[9];
#pragma unroll
    for (int j = 0; j < 9; j++) acc[j] = 0.f;
    for (int k = t; k < Dd; k += 128) {
        float w = whh[(size_t)i * Dd + k];
        const float* jr = je_w + (size_t)k * JEW_LD + Dd;
#pragma unroll
        for (int j = 0; j < 8; j++) acc[j] = fmaf(w, jr[j], acc[j]);
        acc[8] = fmaf(w, je_b[k], acc[8]);
    }
    __shared__ float sh[9][128];
#pragma unroll
    for (int j = 0; j < 9; j++) sh[j][t] = acc[j];
    __syncthreads();
    for (int s = 64; s > 0; s >>= 1) {
        if (t < s)
#pragma unroll
            for (int j = 0; j < 9; j++) sh[j][t] += sh[j][t + s];
        __syncthreads();
    }
    if (t == 0) {
#pragma unroll
        for (int j = 0; j < 8; j++) g_M2[i * 8 + j] = sh[j][0];
        g_c[i] = sh[8][0] + bhh[i];
    }
}

// ---------------- batch stats + BN ------------------------------------------
__global__ void col_stats(const float* __restrict__ X, int M, int N,
                          float* __restrict__ mean, float* __restrict__ var)
{
    const int c = blockIdx.x * 32 + threadIdx.x;
    const int ry = threadIdx.y;
    float s = 0.f, s2 = 0.f;
    for (int r = ry; r < M; r += 8) {
        float v = X[(size_t)r * N + c];
        s += v; s2 += v * v;
    }
    __shared__ float sh[8][32], sh2[8][32];
    sh[ry][threadIdx.x] = s; sh2[ry][threadIdx.x] = s2;
    __syncthreads();
    if (ry == 0) {
#pragma unroll
        for (int y = 1; y < 8; y++) { s += sh[y][threadIdx.x]; s2 += sh2[y][threadIdx.x]; }
        float m = s / (float)M;
        mean[c] = m;
        var[c]  = s2 / (float)M - m * m;
    }
}

__global__ void bn_apply(const float* __restrict__ X, float* __restrict__ Y,
                         const float* __restrict__ mean, const float* __restrict__ var,
                         const float* __restrict__ g, const float* __restrict__ beta,
                         int total, int N, int relu)
{
    int idx = blockIdx.x * blockDim.x + threadIdx.x;
    if (idx >= total) return;
    int c = idx % N;
    float v = g[c] * (X[idx] - mean[c]) * rsqrtf(var[c] + EPSf) + beta[c];
    if (relu) v = fmaxf(v, 0.f);
    Y[idx] = v;
}

__global__ void bn_apply_cvt16(const float* __restrict__ X, float* __restrict__ Yf,
                               f16* __restrict__ Yh,
                               const float* __restrict__ mean, const float* __restrict__ var,
                               const float* __restrict__ g, const float* __restrict__ beta,
                               int total4, int N, int relu)
{
    int i = blockIdx.x * blockDim.x + threadIdx.x;
    if (i >= total4) return;
    int c0 = (i * 4) % N;
    float4 v = ((const float4*)X)[i];
    float o[4] = { v.x, v.y, v.z, v.w };
#pragma unroll
    for (int j = 0; j < 4; j++) {
        int c = c0 + j;
        float t = g[c] * (o[j] - mean[c]) * rsqrtf(var[c] + EPSf) + beta[c];
        if (relu) t = fmaxf(t, 0.f);
        o[j] = t;
    }
    if (Yf) ((float4*)Yf)[i] = make_float4(o[0], o[1], o[2], o[3]);
    __half2* H = (__half2*)Yh;
    H[2*i]   = __halves2half2(__float2half_rn(o[0]), __float2half_rn(o[1]));
    H[2*i+1] = __halves2half2(__float2half_rn(o[2]), __float2half_rn(o[3]));
}

// ---------------- misc ------------------------------------------------------
__global__ void zero_h() {
    int idx = blockIdx.x * blockDim.x + threadIdx.x;
    if (idx == 0) g_bar_cnt = 0u;
    if (idx < Bb * Dd) {
        g_h[idx] = 0.f;
        g_hH[idx] = __float2half_rn(0.f);
    }
}

// ---------------- threefry2x32-20 (JAX partitionable) ------------------------
__device__ __forceinline__ uint32_t rotl32_(uint32_t x, int r) {
    return (x << r) | (x >> (32 - r));
}
__device__ __forceinline__ void threefry2x32_(uint32_t k0, uint32_t k1,
                                              uint32_t& x0, uint32_t& x1)
{
    const uint32_t k2 = k0 ^ k1 ^ 0x1BD11BDAu;
    x0 += k0; x1 += k1;
#define TF_R4(a,b,c,d) \
    x0 += x1; x1 = rotl32_(x1, a); x1 ^= x0; \
    x0 += x1; x1 = rotl32_(x1, b); x1 ^= x0; \
    x0 += x1; x1 = rotl32_(x1, c); x1 ^= x0; \
    x0 += x1; x1 = rotl32_(x1, d); x1 ^= x0;
    TF_R4(13,15,26,6)  x0 += k1; x1 += k2 + 1u;
    TF_R4(17,29,16,24) x0 += k2; x1 += k0 + 2u;
    TF_R4(13,15,26,6)  x0 += k0; x1 += k1 + 3u;
    TF_R4(17,29,16,24) x0 += k1; x1 += k2 + 4u;
    TF_R4(13,15,26,6)  x0 += k2; x1 += k0 + 5u;
#undef TF_R4
}

__global__ void gumbel_softmax_k(float* __restrict__ out)
{
    const int bl = blockIdx.x;
    const int d  = threadIdx.x;
    const int i  = bl * ZDn + d;
    const float logit = g_h[i];

    uint32_t c0 = 0u;
    uint32_t c1 = (uint32_t)i;
    threefry2x32_(0u, 42u, c0, c1);
    const uint32_t bits = c0 ^ c1;
    float f = __uint_as_float((bits >> 9) | 0x3f800000u) - 1.0f;
    const float tiny = 1.1754943508222875e-38f;
    float u = fmaxf(f * (1.0f - tiny) + tiny, tiny);
    float gum = -logf(-logf(u));

    float v = logit + gum;

    __shared__ float red[ZDn];
    red[d] = v; __syncthreads();
    for (int s = ZDn / 2; s > 0; s >>= 1) {
        if (d < s) red[d] = fmaxf(red[d], red[d + s]);
        __syncthreads();
    }
    float mx = red[0];
    __syncthreads();
    float e = expf(v - mx);
    red[d] = e; __syncthreads();
    for (int s = ZDn / 2; s > 0; s >>= 1) {
        if (d < s) red[d] += red[d + s];
        __syncthreads();
    }
    float z = e / red[0];

    out[i] = logit;
    out[Bb * ZLn * ZDn + i] = z;
    g_zH[i] = __float2half_rn(z);
}

// ---------------- launch ------------------------------------------------------
static inline float* symf(const void* s) {
    void* p = nullptr;
    cudaGetSymbolAddress(&p, s);
    return (float*)p;
}
static inline f16* symh(const void* s) {
    void* p = nullptr;
    cudaGetSymbolAddress(&p, s);
    return (f16*)p;
}

extern "C" void kernel_launch(void* const* d_in, const int* in_sizes, int n_in,
                              void* d_out, int out_size)
{
    (void)in_sizes; (void)n_in; (void)out_size;
    const float* obs      = (const float*)d_in[0];
    const float* actions  = (const float*)d_in[1];
    const float* enc_w1   = (const float*)d_in[2];
    const float* enc_b1   = (const float*)d_in[3];
    const float* enc_g1   = (const float*)d_in[4];
    const float* enc_bt1  = (const float*)d_in[5];
    const float* enc_w2   = (const float*)d_in[6];
    const float* enc_b2   = (const float*)d_in[7];
    const float* enc_g2   = (const float*)d_in[8];
    const float* enc_bt2  = (const float*)d_in[9];
    const float* je_w     = (const float*)d_in[10];
    const float* je_b     = (const float*)d_in[11];
    const float* gru_wih  = (const float*)d_in[12];
    const float* gru_bih  = (const float*)d_in[13];
    const float* gru_whh  = (const float*)d_in[14];
    const float* gru_bhh  = (const float*)d_in[15];
    const float* dec_w1   = (const float*)d_in[16];
    const float* dec_b1   = (const float*)d_in[17];
    const float* dec_g1   = (const float*)d_in[18];
    const float* dec_bt1  = (const float*)d_in[19];
    const float* dec_w2   = (const float*)d_in[20];
    const float* dec_b2   = (const float*)d_in[21];
    const float* dec_g2   = (const float*)d_in[22];
    const float* dec_bt2  = (const float*)d_in[23];
    float* out = (float*)d_out;

    float* p_h1 = symf(g_h1);
    float* p_xbn = symf(g_xbn);
    float* p_d1 = symf(g_d1);
    float* p_d2 = symf(g_d2);
    float* p_m  = symf(g_mean);
    float* p_v  = symf(g_var);
    float* p_ws = symf(g_wscan);

    f16 *p_obsH = symh(g_obsH);
    f16 *p_w1 = symh(g_w1);
    f16 *p_h1H = symh(g_h1H);
    f16 *p_w2 = symh(g_w2);
    f16 *p_xH = symh(g_xH);
    f16 *p_wih = symh(g_wih);
    f16 *p_gi16 = symh(g_gi16);
    f16 *p_zH = symh(g_zH);
    f16 *p_d1H = symh(g_d1H);
    f16 *p_dw1 = symh(g_dw1);
    f16 *p_dw2 = symh(g_dw2);

    static cudaStream_t sSide = nullptr;
    static cudaEvent_t evFork = nullptr, evJoin = nullptr;
    static bool attrDone = false;
    if (!attrDone) {
        cudaFuncSetAttribute(mma_gemm16w, cudaFuncAttributeMaxDynamicSharedMemorySize, SMW_BYTES);
        cudaFuncSetAttribute(mma_gemm16, cudaFuncAttributeMaxDynamicSharedMemorySize, SM16_BYTES);
        cudaFuncSetAttribute(mma_scan_persist, cudaFuncAttributeMaxDynamicSharedMemorySize, SSM_BYTES);
        cudaStreamCreateWithFlags(&sSide, cudaStreamNonBlocking);
        cudaEventCreateWithFlags(&evFork, cudaEventDisableTiming);
        cudaEventCreateWithFlags(&evJoin, cudaEventDisableTiming);
        attrDone = true;
    }

    dim3 blk(256);
    dim3 statsBlk(32, 8);

    // ================== FORK: side stream does setup work =====================
    cudaEventRecord(evFork, 0);
    cudaStreamWaitEvent(sSide, evFork, 0);

    cvt16_w<<<(Dd * Hh / 4 + 255) / 256, blk, 0, sSide>>>(enc_w2, p_w2, Dd * Hh / 4);
    cvt16_w<<<(3 * Dd * Dd / 4 + 255) / 256, blk, 0, sSide>>>(gru_wih, p_wih, 3 * Dd * Dd / 4);
    cvt16_w<<<(Hh * Dd / 4 + 255) / 256, blk, 0, sSide>>>(dec_w1, p_dw1, Hh * Dd / 4);
    cvt16_w<<<(OBSn * Hh / 4 + 255) / 256, blk, 0, sSide>>>(dec_w2, p_dw2, OBSn * Hh / 4);
    {
        dim3 grid(Dd / 128, 3 * Dd / 128);
        sgemm_ab<<<grid, blk, 0, sSide>>>(gru_whh, je_w, p_ws, 3 * Dd, Dd, Dd, Dd, JEW_LD, Dd);
        copy_jew<<<(Dd * Dd + 255) / 256, blk, 0, sSide>>>(je_w);
        m2c_k<<<3 * Dd, 128, 0, sSide>>>(gru_whh, je_w, je_b, gru_bhh);
        cvt16_perm_ws<<<(4 * Dd * Dd / 4 + 255) / 256, blk, 0, sSide>>>();
    }
    zero_h<<<(Bb * Dd + 255) / 256, blk, 0, sSide>>>();
    cudaEventRecord(evJoin, sSide);

    // main chain: obs/w1 cvt -> enc1
    cvt16_w<<<(BT * OBSn / 4 + 255) / 256, blk>>>(obs, p_obsH, BT * OBSn / 4);
    cvt16_w<<<(Hh * OBSn / 4 + 255) / 256, blk>>>(enc_w1, p_w1, Hh * OBSn / 4);

    // ---- encoder layer 1 (fp16, wide tile) ----
    {
        dim3 grid(Hh / 256, BT / 128);
        mma_gemm16w<<<grid, blk, SMW_BYTES>>>(p_obsH, p_w1, enc_b1, p_h1, nullptr,
                                              BT, Hh, OBSn);
        col_stats<<<Hh / 32, statsBlk>>>(p_h1, BT, Hh, p_m, p_v);
        bn_apply_cvt16<<<(BT * Hh / 4 + 255) / 256, blk>>>(p_h1, nullptr, p_h1H,
                                                           p_m, p_v, enc_g1, enc_bt1,
                                                           BT * Hh / 4, Hh, 1);
    }

    // ================== JOIN ==================================================
    cudaStreamWaitEvent(0, evJoin, 0);

    // ---- encoder layer 2 (fp16, wide tile) ----
    {
        dim3 grid(Dd / 256, BT / 128);
        mma_gemm16w<<<grid, blk, SMW_BYTES>>>(p_h1H, p_w2, enc_b2, p_xbn, nullptr,
                                              BT, Dd, Hh);
        col_stats<<<Dd / 32, statsBlk>>>(p_xbn, BT, Dd, p_m, p_v);
        bn_apply_cvt16<<<(BT * Dd / 4 + 255) / 256, blk>>>(p_xbn, nullptr, p_xH,
                                                           p_m, p_v, enc_g2, enc_bt2,
                                                           BT * Dd / 4, Dd, 0);
    }
    // ---- gi (fp16, wide tile, fp16 output) ----
    {
        dim3 grid(3 * Dd / 256, BT / 128);
        mma_gemm16w<<<grid, blk, SMW_BYTES>>>(p_xH, p_wih, gru_bih, nullptr, p_gi16,
                                              BT, 3 * Dd, Dd);
    }
    // ---- recurrent scan: ONE persistent kernel (fp16 single-digit) ----
    {
        dim3 gridS(4 * Dd / 64, Bb / 128);   // (64, 2) = 128 CTAs, all resident
        mma_scan_persist<<<gridS, blk, SSM_BYTES>>>(actions, je_w, je_b);
    }
    // ---- gumbel softmax ----
    gumbel_softmax_k<<<Bb * ZLn, ZDn>>>(out);
    // ---- decoder layer 1 (fp16, 128x128) ----
    {
        dim3 grid(Hh / 128, Bb / 128);
        mma_gemm16<<<grid, blk, SM16_BYTES>>>(p_zH, p_dw1, dec_b1, p_d1, Bb, Hh, Dd);
        col_stats<<<Hh / 32, statsBlk>>>(p_d1, Bb, Hh, p_m, p_v);
        bn_apply_cvt16<<<(Bb * Hh / 4 + 255) / 256, blk>>>(p_d1, nullptr, p_d1H,
                                                           p_m, p_v, dec_g1, dec_bt1,
                                                           Bb * Hh / 4, Hh, 1);
    }
    // ---- decoder layer 2 (fp16, 128x128) -> x_hat ----
    {
        dim3 grid(OBSn / 128, Bb / 128);
        mma_gemm16<<<grid, blk, SM16_BYTES>>>(p_d1H, p_dw2, dec_b2, p_d2, Bb, OBSn, Hh);
        col_stats<<<OBSn / 32, statsBlk>>>(p_d2, Bb, OBSn, p_m, p_v);
        int total = Bb * OBSn;
        bn_apply<<<(total + 255) / 256, blk>>>(p_d2, out + 2 * Bb * ZLn * ZDn,
                                               p_m, p_v, dec_g2, dec_bt2, total, OBSn, 0);
    }
}